// round 17
// baseline (speedup 1.0000x reference)
#include <cuda_runtime.h>
#include <cuda_fp16.h>
#include <cstdint>

#define LAYERS 8
#define T      512
#define B      64
#define H      256
#define G      1024
#define VOCAB  23
#define EMB    16
#define NC     16
#define THR    256

#define WSTR   528            // bytes per padded row (264 fp16)

// smem byte offsets
#define SB_BUF0   0           // staging h plane / transient W prep
#define SB_BUF1   33792
#define SB_GX     67584       // f32 [64][68]
#define SB_GX2    84992       // f32 [64][68]
#define SB_CST    102400      // f32 [16][68]
#define SB_TAB    106752      // float4 [23*16]
#define SB_BIAS   112640      // float4 [16]
#define SB_TOK    112896      // int [64]
#define SMEM_BYTES 113152

static __device__ __align__(128) __half g_hbf[(size_t)LAYERS * T * 16384];   // [l][t][b][k] fp16
static __device__ float g_hseq7[(size_t)T * H * B];
static __device__ float g_table[VOCAB * G];
static __device__ int   g_prog[LAYERS * NC];    // per-CTA progress: steps completed

// ---------- helpers ----------
__device__ __forceinline__ uint32_t smem_u32(const void* p) {
    uint32_t a;
    asm("{ .reg .u64 t; cvta.to.shared.u64 t, %1; cvt.u32.u64 %0, t; }" : "=r"(a) : "l"(p));
    return a;
}
__device__ __forceinline__ float tanha(float x) {
    float y; asm("tanh.approx.f32 %0, %1;" : "=f"(y) : "f"(x));
    return y;
}
__device__ __forceinline__ float sigm(float x) { return fmaf(0.5f, tanha(0.5f * x), 0.5f); }

#define LDSM4(r0,r1,r2,r3,addr) \
    asm volatile("ldmatrix.sync.aligned.m8n8.x4.shared.b16 {%0,%1,%2,%3}, [%4];" \
                 : "=r"(r0),"=r"(r1),"=r"(r2),"=r"(r3) : "r"(addr))

#define MMA16816(c, a0,a1,a2,a3, b0,b1) \
    asm volatile("mma.sync.aligned.m16n8k16.row.col.f32.f16.f16.f32 " \
                 "{%0,%1,%2,%3},{%4,%5,%6,%7},{%8,%9},{%0,%1,%2,%3};" \
                 : "+f"((c)[0]),"+f"((c)[1]),"+f"((c)[2]),"+f"((c)[3]) \
                 : "r"(a0),"r"(a1),"r"(a2),"r"(a3),"r"(b0),"r"(b1))

// Load this warp's persisted W fragments (8 k16 x 8 regs) from a padded smem plane.
__device__ __forceinline__ void load_wfrags(uint32_t (&wa)[8][8], uint32_t planeP, uint32_t ar) {
#pragma unroll
    for (int k = 0; k < 8; ++k) {
        LDSM4(wa[k][0],wa[k][1],wa[k][2],wa[k][3], planeP + ar + k * 32);
        LDSM4(wa[k][4],wa[k][5],wa[k][6],wa[k][7], planeP + ar + 16 * WSTR + k * 32);
    }
}

// Single-term pass: acc += W(regs) * B(smem) over 8 k16 chunks; B double-buffered.
__device__ __forceinline__ void pass1t(
    const uint32_t (&wa)[8][8], uint32_t bufP, float (&acc)[2][4][4], uint32_t br)
{
    const uint32_t bP = bufP + br;
    uint32_t fb[2][8];
    LDSM4(fb[0][0],fb[0][1],fb[0][2],fb[0][3], bP);
    LDSM4(fb[0][4],fb[0][5],fb[0][6],fb[0][7], bP + 16 * WSTR);
#pragma unroll
    for (int k = 0; k < 8; ++k) {
        const int cur = k & 1;
        if (k < 7) {
            const int nx = cur ^ 1;
            LDSM4(fb[nx][0],fb[nx][1],fb[nx][2],fb[nx][3], bP + (k+1)*32);
            LDSM4(fb[nx][4],fb[nx][5],fb[nx][6],fb[nx][7], bP + 16*WSTR + (k+1)*32);
        }
#pragma unroll
        for (int mh = 0; mh < 2; ++mh) {
            const uint32_t* ah = &wa[k][mh * 4];
            const uint32_t* b  = fb[cur];
            MMA16816(acc[mh][0], ah[0],ah[1],ah[2],ah[3], b[0],b[2]);
            MMA16816(acc[mh][1], ah[0],ah[1],ah[2],ah[3], b[1],b[3]);
            MMA16816(acc[mh][2], ah[0],ah[1],ah[2],ah[3], b[4],b[6]);
            MMA16816(acc[mh][3], ah[0],ah[1],ah[2],ah[3], b[5],b[7]);
        }
    }
}

// async-stage one dense 32KB global plane into a padded smem plane; commits a group.
__device__ __forceinline__ void stage(uint32_t dstS, const char* src, int tid) {
#pragma unroll
    for (int u = 0; u < 8; ++u) {
        int i = tid + u * THR;
        int b = i >> 5, kc = i & 31;
        asm volatile("cp.async.cg.shared.global [%0], [%1], 16;"
                     :: "r"(dstS + (uint32_t)(b * WSTR + kc * 16)),
                        "l"(src + b * 512 + kc * 16) : "memory");
    }
    asm volatile("cp.async.commit_group;" ::: "memory");
}
#define CP_WAIT1() asm volatile("cp.async.wait_group 1;" ::: "memory")
#define CP_WAIT0() asm volatile("cp.async.wait_group 0;" ::: "memory")

// ---------- prelude ----------
__global__ void zero_prog_kernel() {
    int i = blockIdx.x * blockDim.x + threadIdx.x;
    if (i < LAYERS * NC) g_prog[i] = 0;
}
__global__ void build_table_kernel(const float* __restrict__ emb, const float* __restrict__ Wih0,
                                   const float* __restrict__ bih, const float* __restrict__ bhh) {
    int idx = blockIdx.x * blockDim.x + threadIdx.x;
    if (idx >= VOCAB * G) return;
    int v = idx / G, j = idx % G;
    float s = bih[j] + bhh[j];
#pragma unroll
    for (int e = 0; e < EMB; ++e) s += emb[v * EMB + e] * Wih0[j * EMB + e];
    g_table[idx] = s;
}

// ---------- main persistent wavefront kernel ----------
extern "C" __global__ void __launch_bounds__(THR, 1)
lstm_main_kernel(const int* __restrict__ x,
                 const float* __restrict__ Wih_rest,
                 const float* __restrict__ Whh,
                 const float* __restrict__ bih,
                 const float* __restrict__ bhh)
{
    extern __shared__ char smem[];
    const uint32_t sb = smem_u32(smem);
    const int tid  = threadIdx.x;
    const int warp = tid >> 5, lane = tid & 31;
    const int l = blockIdx.x >> 4;
    const int c = blockIdx.x & 15;          // unit block: units c*16 .. c*16+15
    const int kh = warp >> 2, mi = (warp >> 1) & 1, ni = warp & 1;

    float*  gx    = (float*)(smem + SB_GX);     // [64][68]
    float*  gx2   = (float*)(smem + SB_GX2);    // [64][68]
    float*  cst   = (float*)(smem + SB_CST);    // [16][68]
    float4* tab4  = (float4*)(smem + SB_TAB);
    float4* bias4 = (float4*)(smem + SB_BIAS);
    int*    tokI  = (int*)(smem + SB_TOK);

    // per-warp fragment base offsets
    const uint32_t kOff = (uint32_t)(kh * 256) + ((lane >> 4) << 4);
    const uint32_t ar = (uint32_t)(mi * 32 + (lane & 15)) * WSTR + kOff;
    const uint32_t br = (uint32_t)(ni * 32 + (lane & 15)) * WSTR + kOff;

    // ---- weight prep: fp16 W -> BUF0/BUF1 (transient) ----
    {
        const float* Wl = Whh + (size_t)l * G * H;
        for (int idx = tid; idx < 64 * 256; idx += THR) {
            int r = idx >> 8, k = idx & 255;
            int jg = (r >> 4) * H + c * 16 + (r & 15);
            *(__half*)(smem + SB_BUF0 + r * WSTR + k * 2) =
                __float2half_rn(Wl[(size_t)jg * H + k]);
        }
    }
    if (l > 0) {
        const float* Wl = Wih_rest + (size_t)(l - 1) * G * H;
        for (int idx = tid; idx < 64 * 256; idx += THR) {
            int r = idx >> 8, k = idx & 255;
            int jg = (r >> 4) * H + c * 16 + (r & 15);
            *(__half*)(smem + SB_BUF1 + r * WSTR + k * 2) =
                __float2half_rn(Wl[(size_t)jg * H + k]);
        }
        if (tid < 16) {
            int u = tid;
            float4 q;
            q.x = bih[l * G + 0 * H + c * 16 + u] + bhh[l * G + 0 * H + c * 16 + u];
            q.y = bih[l * G + 1 * H + c * 16 + u] + bhh[l * G + 1 * H + c * 16 + u];
            q.z = bih[l * G + 2 * H + c * 16 + u] + bhh[l * G + 2 * H + c * 16 + u];
            q.w = bih[l * G + 3 * H + c * 16 + u] + bhh[l * G + 3 * H + c * 16 + u];
            bias4[u] = q;
        }
    } else {
        for (int idx = tid; idx < VOCAB * 16; idx += THR) {
            int v = idx >> 4, u = idx & 15;
            float4 q;
            q.x = g_table[v * G + 0 * H + c * 16 + u];
            q.y = g_table[v * G + 1 * H + c * 16 + u];
            q.z = g_table[v * G + 2 * H + c * 16 + u];
            q.w = g_table[v * G + 3 * H + c * 16 + u];
            tab4[idx] = q;
        }
    }
    __syncthreads();

    // ---- persist W fragments in registers for the whole run ----
    uint32_t whh_w[8][8], wih_w[8][8];
    load_wfrags(whh_w, sb + SB_BUF0, ar);
    if (l > 0) load_wfrags(wih_w, sb + SB_BUF1, ar);
    else {
#pragma unroll
        for (int k = 0; k < 8; ++k)
#pragma unroll
            for (int j = 0; j < 8; ++j) wih_w[k][j] = 0;
    }
    __syncthreads();   // BUF0/BUF1 free for staging

    for (int t = 0; t < T; ++t) {
        if (l == 0 && tid < 64) tokI[tid] = x[tid * T + t];

        float acc[2][4][4];
#pragma unroll
        for (int a = 0; a < 2; ++a)
#pragma unroll
            for (int b = 0; b < 4; ++b)
#pragma unroll
                for (int q = 0; q < 4; ++q) acc[a][b][q] = 0.f;

        const bool rec = (t > 0), inp = (l > 0);
        const char* recsrc = (const char*)g_hbf + (size_t)(l * T + t - 1) * 32768;
        const char* insrc  = (const char*)g_hbf + (size_t)((l - 1) * T + t) * 32768;

        if (rec || inp) {
            // merged wait: threads 0-15 poll producer layer, 16-31 poll own-layer siblings
            if (tid < 16) {
                if (inp) {
                    volatile int* p = &g_prog[(l - 1) * NC + tid];
                    while (*p < t + 1) __nanosleep(32);
                }
            } else if (tid < 32) {
                if (rec) {
                    volatile int* p = &g_prog[l * NC + (tid - 16)];
                    while (*p < t) __nanosleep(32);
                }
            }
            __syncthreads();

            if (inp) stage(sb + SB_BUF1, insrc, tid);     // group A (committed first)
            if (rec) stage(sb + SB_BUF0, recsrc, tid);    // group B

            if (rec && inp) {
                CP_WAIT1(); __syncthreads();              // buf1 (in_h) ready
                pass1t(wih_w, sb + SB_BUF1, acc, br);     // rec staging still in flight
                CP_WAIT0(); __syncthreads();              // buf0 (rec_h) ready
                pass1t(whh_w, sb + SB_BUF0, acc, br);
            } else if (rec) {
                CP_WAIT0(); __syncthreads();
                pass1t(whh_w, sb + SB_BUF0, acc, br);
            } else {
                CP_WAIT0(); __syncthreads();
                pass1t(wih_w, sb + SB_BUF1, acc, br);
            }
        }

        // ---- split-K store (kh=0 -> gx, kh=1 -> gx2), then single barrier ----
        {
            float* dst = (kh == 0) ? gx : gx2;
#pragma unroll
            for (int ms = 0; ms < 2; ++ms) {
                int m = mi * 32 + ms * 16 + (lane >> 2);
#pragma unroll
                for (int ns = 0; ns < 4; ++ns) {
                    int b = ni * 32 + ns * 8 + (lane & 3) * 2;
                    *(float2*)(dst + m * 68 + b)       = make_float2(acc[ms][ns][0], acc[ms][ns][1]);
                    *(float2*)(dst + (m + 8) * 68 + b) = make_float2(acc[ms][ns][2], acc[ms][ns][3]);
                }
            }
        }
        __syncthreads();   // gx/gx2 visible; BUF reads done before next-step staging

        // ---- cell update: thread = (u, 4 b's); coalesced fp16 h publish ----
        {
            const int u = tid & 15, grp = tid >> 4;
            char* dstP = (char*)g_hbf + (size_t)(l * T + t) * 32768;
            const int k = c * 16 + u;
            float4 bq = (l > 0) ? bias4[u] : make_float4(0.f, 0.f, 0.f, 0.f);
#pragma unroll
            for (int i = 0; i < 4; ++i) {
                int b = grp * 4 + i;
                float4 q = (l == 0) ? tab4[tokI[b] * 16 + u] : bq;
                float ig = gx[(0 * 16 + u) * 68 + b] + gx2[(0 * 16 + u) * 68 + b] + q.x;
                float fg = gx[(1 * 16 + u) * 68 + b] + gx2[(1 * 16 + u) * 68 + b] + q.y;
                float gg = gx[(2 * 16 + u) * 68 + b] + gx2[(2 * 16 + u) * 68 + b] + q.z;
                float og = gx[(3 * 16 + u) * 68 + b] + gx2[(3 * 16 + u) * 68 + b] + q.w;
                float cv = (t == 0) ? 0.f : cst[u * 68 + b];
                float cn = sigm(fg) * cv + sigm(ig) * tanha(gg);
                cst[u * 68 + b] = cn;
                float hv = sigm(og) * tanha(cn);
                *(__half*)(dstP + b * 512 + k * 2) = __float2half_rn(hv);
                if (l == 7) g_hseq7[(size_t)t * 16384 + k * 64 + b] = hv;
            }
        }
        __syncthreads();                 // all h stores issued
        if (tid == 0) {
            __threadfence();             // fence in one thread only (after barrier)
            *(volatile int*)&g_prog[l * NC + c] = t + 1;
        }
    }
}

// ---------- final FC ----------
#define FC_SMEM_FLOATS (256 * 64 + 256 * 24 + 32)
__global__ void __launch_bounds__(256)
fc_kernel(const float* __restrict__ fcw, const float* __restrict__ fcb,
          float* __restrict__ out)
{
    extern __shared__ float fsm[];
    float* hs = fsm;
    float* ws = fsm + 256 * 64;
    float* bs = ws + 256 * 24;
    const int tid = threadIdx.x, t = blockIdx.x;

    const float* h7 = g_hseq7 + (size_t)t * H * B;
    {
        const float4* s = (const float4*)h7;
        float4* d = (float4*)hs;
        for (int i = tid; i < 4096; i += 256) d[i] = s[i];
    }
    for (int i = tid; i < VOCAB * H; i += 256) {
        int v = i >> 8, k = i & 255;
        ws[k * 24 + v] = fcw[i];
    }
    if (tid < VOCAB) bs[tid] = fcb[tid];
    __syncthreads();

    const int b = tid & 63, vg = tid >> 6;
    const int v0 = vg * 6;
    const int nv = (v0 + 6 <= VOCAB) ? 6 : (VOCAB - v0);
    float acc[6] = {0.f, 0.f, 0.f, 0.f, 0.f, 0.f};
#pragma unroll 4
    for (int k = 0; k < 256; ++k) {
        float a = hs[k * 64 + b];
#pragma unroll
        for (int j = 0; j < 6; ++j) acc[j] += a * ws[k * 24 + v0 + j];
    }
    for (int j = 0; j < nv; ++j)
        out[((size_t)b * T + t) * VOCAB + v0 + j] = acc[j] + bs[v0 + j];
}

// ---------- launch ----------
extern "C" void kernel_launch(void* const* d_in, const int* in_sizes, int n_in,
                              void* d_out, int out_size)
{
    const int*   x        = (const int*)d_in[0];
    const float* emb      = (const float*)d_in[1];
    const float* Wih0     = (const float*)d_in[2];
    const float* Wih_rest = (const float*)d_in[3];
    const float* Whh      = (const float*)d_in[4];
    const float* bih      = (const float*)d_in[5];
    const float* bhh      = (const float*)d_in[6];
    const float* fcw      = (const float*)d_in[7];
    const float* fcb      = (const float*)d_in[8];
    float*       out      = (float*)d_out;

    cudaFuncSetAttribute(lstm_main_kernel,
                         cudaFuncAttributeMaxDynamicSharedMemorySize, SMEM_BYTES);
    cudaFuncSetAttribute(fc_kernel,
                         cudaFuncAttributeMaxDynamicSharedMemorySize, FC_SMEM_FLOATS * 4);

    zero_prog_kernel<<<1, 256>>>();
    build_table_kernel<<<(VOCAB * G + 255) / 256, 256>>>(emb, Wih0, bih, bhh);
    lstm_main_kernel<<<LAYERS * NC, THR, SMEM_BYTES>>>(x, Wih_rest, Whh, bih, bhh);
    fc_kernel<<<T, 256, FC_SMEM_FLOATS * 4>>>(fcw, fcb, out);
}